// round 14
// baseline (speedup 1.0000x reference)
#include <cuda_runtime.h>
#include <math.h>

#define NE   32      // experts
#define TK   4       // top_k
#define D    1024    // hidden
#define F    2048    // ffn
#define NTOK 1024    // batch*seq

#define BM 128
#define BN 128
#define BK 16

// ---------------- device scratch (static, allocation-free) ----------------
__device__ float g_probs_sum[NE];          // sum over tokens of softmax probs
__device__ int   g_cnt[NE];                // assignments per expert
__device__ int   g_tok[NE * NTOK];         // token id per assignment
__device__ int   g_slot[NE * NTOK];        // global slot = tok*TK + choice
__device__ float g_wt[NE * NTOK];          // combine weight per assignment
__device__ float g_hbuf[NTOK * TK * F];    // 32 MB intermediate h (gelu(xW1+b1))

// ---------------- zero init ----------------
__global__ void zero_kernel(float* __restrict__ out, int n) {
    int i = blockIdx.x * blockDim.x + threadIdx.x;
    if (i < n) out[i] = 0.0f;
    if (i < NE) { g_probs_sum[i] = 0.0f; g_cnt[i] = 0; }
}

// ---------------- router: one block (32 lanes) per token ----------------
__global__ void router_kernel(const float* __restrict__ x,
                              const float* __restrict__ gw,
                              const float* __restrict__ gb) {
    int tok = blockIdx.x;
    int e   = threadIdx.x;                 // 0..31, one expert per lane
    const float* xr = x + (size_t)tok * D;

    float a0 = 0.f, a1 = 0.f, a2 = 0.f, a3 = 0.f;
    #pragma unroll 8
    for (int h = 0; h < D; h += 4) {
        a0 = fmaf(xr[h + 0], gw[(h + 0) * NE + e], a0);
        a1 = fmaf(xr[h + 1], gw[(h + 1) * NE + e], a1);
        a2 = fmaf(xr[h + 2], gw[(h + 2) * NE + e], a2);
        a3 = fmaf(xr[h + 3], gw[(h + 3) * NE + e], a3);
    }
    float logit = (a0 + a1) + (a2 + a3) + gb[e];

    // full softmax prob (for aux loss)
    float m = logit;
    #pragma unroll
    for (int o = 16; o; o >>= 1) m = fmaxf(m, __shfl_xor_sync(0xffffffffu, m, o));
    float ex = expf(logit - m);
    float s = ex;
    #pragma unroll
    for (int o = 16; o; o >>= 1) s += __shfl_xor_sync(0xffffffffu, s, o);
    atomicAdd(&g_probs_sum[e], ex / s);

    // iterative top-4 argmax (strict >, lowest index on tie = jax top_k)
    float v = logit;
    float tv0, tv1, tv2, tv3;
    int   ti0, ti1, ti2, ti3;
    #pragma unroll
    for (int k = 0; k < TK; k++) {
        float mv = v; int mi = e;
        #pragma unroll
        for (int o = 16; o; o >>= 1) {
            float ov = __shfl_xor_sync(0xffffffffu, mv, o);
            int   oi = __shfl_xor_sync(0xffffffffu, mi, o);
            if (ov > mv || (ov == mv && oi < mi)) { mv = ov; mi = oi; }
        }
        if (k == 0) { tv0 = mv; ti0 = mi; }
        else if (k == 1) { tv1 = mv; ti1 = mi; }
        else if (k == 2) { tv2 = mv; ti2 = mi; }
        else { tv3 = mv; ti3 = mi; }
        if (e == mi) v = -INFINITY;
    }
    // softmax over the 4 selected logits (tv0 is the max)
    float se = expf(tv0 - tv0) + expf(tv1 - tv0) + expf(tv2 - tv0) + expf(tv3 - tv0);

    if (e < TK) {
        float tv = tv0; int ti = ti0;
        if (e == 1) { tv = tv1; ti = ti1; }
        else if (e == 2) { tv = tv2; ti = ti2; }
        else if (e == 3) { tv = tv3; ti = ti3; }
        float w = expf(tv - tv0) / se;
        int pos = atomicAdd(&g_cnt[ti], 1);
        g_tok[ti * NTOK + pos]  = tok;
        g_slot[ti * NTOK + pos] = tok * TK + e;
        g_wt[ti * NTOK + pos]   = w;
    }
}

// ---------------- GEMM1: H[slot] = gelu(x[tok] @ w1[e] + b1[e]) ----------------
__global__ __launch_bounds__(256) void gemm1_kernel(
    const float* __restrict__ x, const float* __restrict__ w1,
    const float* __restrict__ b1) {
    int e    = blockIdx.z;
    int cnt  = g_cnt[e];
    int row0 = blockIdx.y * BM;
    if (row0 >= cnt) return;
    int col0 = blockIdx.x * BN;

    __shared__ float As[BK][BM];
    __shared__ float Bs[BK][BN];
    __shared__ int   rows[BM];

    int tid = threadIdx.x;
    if (tid < BM) {
        int r = row0 + tid;
        rows[tid] = (r < cnt) ? g_tok[e * NTOK + r] : -1;
    }
    __syncthreads();

    int ty = tid >> 4, tx = tid & 15;
    float acc[8][8];
    #pragma unroll
    for (int i = 0; i < 8; i++)
        #pragma unroll
        for (int j = 0; j < 8; j++) acc[i][j] = 0.f;

    // A-load assignment: thread handles row ar, cols [ac, ac+8)
    int ar = tid >> 1;
    int ac = (tid & 1) * 8;
    int atok = rows[ar];
    // B-load assignment: row br, cols [bc, bc+8)
    int br = tid >> 4;
    int bc = (tid & 15) * 8;

    const float* Bbase = w1 + (size_t)e * D * F + col0;

    for (int k0 = 0; k0 < D; k0 += BK) {
        float4 av0 = make_float4(0.f, 0.f, 0.f, 0.f), av1 = av0;
        if (atok >= 0) {
            const float4* ap = (const float4*)(x + (size_t)atok * D + k0 + ac);
            av0 = ap[0]; av1 = ap[1];
        }
        const float4* bp = (const float4*)(Bbase + (size_t)(k0 + br) * F + bc);
        float4 bv0 = bp[0], bv1 = bp[1];

        As[ac + 0][ar] = av0.x; As[ac + 1][ar] = av0.y;
        As[ac + 2][ar] = av0.z; As[ac + 3][ar] = av0.w;
        As[ac + 4][ar] = av1.x; As[ac + 5][ar] = av1.y;
        As[ac + 6][ar] = av1.z; As[ac + 7][ar] = av1.w;
        *(float4*)&Bs[br][bc]     = bv0;
        *(float4*)&Bs[br][bc + 4] = bv1;
        __syncthreads();

        #pragma unroll
        for (int k = 0; k < BK; k++) {
            float4 A0 = *(const float4*)&As[k][ty * 4];
            float4 A1 = *(const float4*)&As[k][ty * 4 + 64];
            float4 B0 = *(const float4*)&Bs[k][tx * 4];
            float4 B1 = *(const float4*)&Bs[k][tx * 4 + 64];
            float axv[8] = {A0.x, A0.y, A0.z, A0.w, A1.x, A1.y, A1.z, A1.w};
            float bxv[8] = {B0.x, B0.y, B0.z, B0.w, B1.x, B1.y, B1.z, B1.w};
            #pragma unroll
            for (int i = 0; i < 8; i++)
                #pragma unroll
                for (int j = 0; j < 8; j++)
                    acc[i][j] = fmaf(axv[i], bxv[j], acc[i][j]);
        }
        __syncthreads();
    }

    // epilogue: bias + exact-erf gelu -> hbuf
    #pragma unroll
    for (int i = 0; i < 8; i++) {
        int rloc = (i < 4) ? (ty * 4 + i) : (64 + ty * 4 + (i - 4));
        int r = row0 + rloc;
        if (r >= cnt) continue;
        int slot = g_slot[e * NTOK + r];
        float* hrow = g_hbuf + (size_t)slot * F + col0;
        #pragma unroll
        for (int j = 0; j < 8; j++) {
            int cloc = (j < 4) ? (tx * 4 + j) : (64 + tx * 4 + (j - 4));
            float val = acc[i][j] + b1[e * F + col0 + cloc];
            hrow[cloc] = 0.5f * val * (1.0f + erff(val * 0.70710678118654752f));
        }
    }
}

// ---------------- GEMM2: out[tok] += ce * (H[slot] @ w2[e] + b2[e]) ----------------
__global__ __launch_bounds__(256) void gemm2_kernel(
    const float* __restrict__ w2, const float* __restrict__ b2,
    float* __restrict__ out) {
    int e    = blockIdx.z;
    int cnt  = g_cnt[e];
    int row0 = blockIdx.y * BM;
    if (row0 >= cnt) return;
    int col0 = blockIdx.x * BN;

    __shared__ float As[BK][BM];
    __shared__ float Bs[BK][BN];
    __shared__ int   slots[BM];
    __shared__ int   toks[BM];
    __shared__ float wts[BM];

    int tid = threadIdx.x;
    if (tid < BM) {
        int r = row0 + tid;
        if (r < cnt) {
            slots[tid] = g_slot[e * NTOK + r];
            toks[tid]  = g_tok[e * NTOK + r];
            wts[tid]   = g_wt[e * NTOK + r];
        } else {
            slots[tid] = -1; toks[tid] = 0; wts[tid] = 0.f;
        }
    }
    __syncthreads();

    int ty = tid >> 4, tx = tid & 15;
    float acc[8][8];
    #pragma unroll
    for (int i = 0; i < 8; i++)
        #pragma unroll
        for (int j = 0; j < 8; j++) acc[i][j] = 0.f;

    int ar = tid >> 1;
    int ac = (tid & 1) * 8;
    int aslot = slots[ar];
    int br = tid >> 4;
    int bc = (tid & 15) * 8;

    const float* Bbase = w2 + (size_t)e * F * D + col0;

    for (int k0 = 0; k0 < F; k0 += BK) {
        float4 av0 = make_float4(0.f, 0.f, 0.f, 0.f), av1 = av0;
        if (aslot >= 0) {
            const float4* ap = (const float4*)(g_hbuf + (size_t)aslot * F + k0 + ac);
            av0 = ap[0]; av1 = ap[1];
        }
        const float4* bp = (const float4*)(Bbase + (size_t)(k0 + br) * D + bc);
        float4 bv0 = bp[0], bv1 = bp[1];

        As[ac + 0][ar] = av0.x; As[ac + 1][ar] = av0.y;
        As[ac + 2][ar] = av0.z; As[ac + 3][ar] = av0.w;
        As[ac + 4][ar] = av1.x; As[ac + 5][ar] = av1.y;
        As[ac + 6][ar] = av1.z; As[ac + 7][ar] = av1.w;
        *(float4*)&Bs[br][bc]     = bv0;
        *(float4*)&Bs[br][bc + 4] = bv1;
        __syncthreads();

        #pragma unroll
        for (int k = 0; k < BK; k++) {
            float4 A0 = *(const float4*)&As[k][ty * 4];
            float4 A1 = *(const float4*)&As[k][ty * 4 + 64];
            float4 B0 = *(const float4*)&Bs[k][tx * 4];
            float4 B1 = *(const float4*)&Bs[k][tx * 4 + 64];
            float axv[8] = {A0.x, A0.y, A0.z, A0.w, A1.x, A1.y, A1.z, A1.w};
            float bxv[8] = {B0.x, B0.y, B0.z, B0.w, B1.x, B1.y, B1.z, B1.w};
            #pragma unroll
            for (int i = 0; i < 8; i++)
                #pragma unroll
                for (int j = 0; j < 8; j++)
                    acc[i][j] = fmaf(axv[i], bxv[j], acc[i][j]);
        }
        __syncthreads();
    }

    #pragma unroll
    for (int i = 0; i < 8; i++) {
        int rloc = (i < 4) ? (ty * 4 + i) : (64 + ty * 4 + (i - 4));
        int r = row0 + rloc;
        if (r >= cnt) continue;
        int tok = toks[rloc];
        float w = wts[rloc];
        float* orow = out + (size_t)tok * D + col0;
        #pragma unroll
        for (int j = 0; j < 8; j++) {
            int cloc = (j < 4) ? (tx * 4 + j) : (64 + tx * 4 + (j - 4));
            float val = (acc[i][j] + b2[e * D + col0 + cloc]) * w;
            atomicAdd(&orow[cloc], val);
        }
    }
}

// ---------------- aux loss scalar ----------------
__global__ void aux_kernel(const float* __restrict__ load_ema,
                           float* __restrict__ out_aux) {
    float base = 0.f;
    for (int e = 0; e < NE; e++) {
        float frac = ((float)g_cnt[e] / (float)NTOK) / (float)TK;
        float pm   = g_probs_sum[e] / (float)NTOK;
        base += frac * pm;
    }
    base *= (float)NE;
    float s = 0.f;
    for (int e = 0; e < NE; e++) s += load_ema[e];
    float ent = 0.f;
    for (int e = 0; e < NE; e++) {
        float lp = load_ema[e] / (s + 1e-8f);
        ent -= lp * logf(lp + 1e-8f);
    }
    float reg = logf((float)NE) - ent;
    out_aux[0] = base + 0.001f * reg;
}

// ---------------- launch ----------------
extern "C" void kernel_launch(void* const* d_in, const int* in_sizes, int n_in,
                              void* d_out, int out_size) {
    const float* x   = (const float*)d_in[0];
    const float* gw  = (const float*)d_in[1];
    const float* gb  = (const float*)d_in[2];
    const float* w1  = (const float*)d_in[3];
    const float* b1  = (const float*)d_in[4];
    const float* w2  = (const float*)d_in[5];
    const float* b2  = (const float*)d_in[6];
    const float* ema = (const float*)d_in[7];
    float* out = (float*)d_out;

    const int nOut = NTOK * D;

    zero_kernel<<<(nOut + 255) / 256, 256>>>(out, nOut);
    router_kernel<<<NTOK, 32>>>(x, gw, gb);
    gemm1_kernel<<<dim3(F / BN, NTOK / BM, NE), 256>>>(x, w1, b1);
    gemm2_kernel<<<dim3(D / BN, NTOK / BM, NE), 256>>>(w2, b2, out);
    if (out_size > nOut) {
        aux_kernel<<<1, 1>>>(ema, out + nOut);
    }
}

// round 15
// speedup vs baseline: 1.0015x; 1.0015x over previous
#include <cuda_runtime.h>
#include <math.h>

#define NE   32      // experts
#define TK   4       // top_k
#define D    1024    // hidden
#define F    2048    // ffn
#define NTOK 1024    // batch*seq

#define BM 128
#define BN 128
#define BK 16

// ---------------- device scratch (static, allocation-free) ----------------
__device__ float g_probs_sum[NE];          // sum over tokens of softmax probs
__device__ int   g_cnt[NE];                // assignments per expert
__device__ int   g_tok[NE * NTOK];         // token id per assignment
__device__ int   g_slot[NE * NTOK];        // global slot = tok*TK + choice
__device__ float g_wt[NE * NTOK];          // combine weight per assignment
__device__ float g_hbuf[NTOK * TK * F];    // 32 MB intermediate h (gelu(xW1+b1))

// ---------------- zero init ----------------
__global__ void zero_kernel(float* __restrict__ out, int n) {
    int i = blockIdx.x * blockDim.x + threadIdx.x;
    if (i < n) out[i] = 0.0f;
    if (i < NE) { g_probs_sum[i] = 0.0f; g_cnt[i] = 0; }
}

// ---------------- router: one block (32 lanes) per token ----------------
__global__ void router_kernel(const float* __restrict__ x,
                              const float* __restrict__ gw,
                              const float* __restrict__ gb) {
    int tok = blockIdx.x;
    int e   = threadIdx.x;                 // 0..31, one expert per lane
    const float* xr = x + (size_t)tok * D;

    float a0 = 0.f, a1 = 0.f, a2 = 0.f, a3 = 0.f;
    #pragma unroll 8
    for (int h = 0; h < D; h += 4) {
        a0 = fmaf(xr[h + 0], gw[(h + 0) * NE + e], a0);
        a1 = fmaf(xr[h + 1], gw[(h + 1) * NE + e], a1);
        a2 = fmaf(xr[h + 2], gw[(h + 2) * NE + e], a2);
        a3 = fmaf(xr[h + 3], gw[(h + 3) * NE + e], a3);
    }
    float logit = (a0 + a1) + (a2 + a3) + gb[e];

    // full softmax prob (for aux loss)
    float m = logit;
    #pragma unroll
    for (int o = 16; o; o >>= 1) m = fmaxf(m, __shfl_xor_sync(0xffffffffu, m, o));
    float ex = expf(logit - m);
    float s = ex;
    #pragma unroll
    for (int o = 16; o; o >>= 1) s += __shfl_xor_sync(0xffffffffu, s, o);
    atomicAdd(&g_probs_sum[e], ex / s);

    // iterative top-4 argmax (strict >, lowest index on tie = jax top_k)
    float v = logit;
    float tv0, tv1, tv2, tv3;
    int   ti0, ti1, ti2, ti3;
    #pragma unroll
    for (int k = 0; k < TK; k++) {
        float mv = v; int mi = e;
        #pragma unroll
        for (int o = 16; o; o >>= 1) {
            float ov = __shfl_xor_sync(0xffffffffu, mv, o);
            int   oi = __shfl_xor_sync(0xffffffffu, mi, o);
            if (ov > mv || (ov == mv && oi < mi)) { mv = ov; mi = oi; }
        }
        if (k == 0) { tv0 = mv; ti0 = mi; }
        else if (k == 1) { tv1 = mv; ti1 = mi; }
        else if (k == 2) { tv2 = mv; ti2 = mi; }
        else { tv3 = mv; ti3 = mi; }
        if (e == mi) v = -INFINITY;
    }
    // softmax over the 4 selected logits (tv0 is the max)
    float se = expf(tv0 - tv0) + expf(tv1 - tv0) + expf(tv2 - tv0) + expf(tv3 - tv0);

    if (e < TK) {
        float tv = tv0; int ti = ti0;
        if (e == 1) { tv = tv1; ti = ti1; }
        else if (e == 2) { tv = tv2; ti = ti2; }
        else if (e == 3) { tv = tv3; ti = ti3; }
        float w = expf(tv - tv0) / se;
        int pos = atomicAdd(&g_cnt[ti], 1);
        g_tok[ti * NTOK + pos]  = tok;
        g_slot[ti * NTOK + pos] = tok * TK + e;
        g_wt[ti * NTOK + pos]   = w;
    }
}

// ---------------- GEMM1: H[slot] = gelu(x[tok] @ w1[e] + b1[e]) ----------------
__global__ __launch_bounds__(256) void gemm1_kernel(
    const float* __restrict__ x, const float* __restrict__ w1,
    const float* __restrict__ b1) {
    int e    = blockIdx.z;
    int cnt  = g_cnt[e];
    int row0 = blockIdx.y * BM;
    if (row0 >= cnt) return;
    int col0 = blockIdx.x * BN;

    __shared__ float As[BK][BM];
    __shared__ float Bs[BK][BN];
    __shared__ int   rows[BM];

    int tid = threadIdx.x;
    if (tid < BM) {
        int r = row0 + tid;
        rows[tid] = (r < cnt) ? g_tok[e * NTOK + r] : -1;
    }
    __syncthreads();

    int ty = tid >> 4, tx = tid & 15;
    float acc[8][8];
    #pragma unroll
    for (int i = 0; i < 8; i++)
        #pragma unroll
        for (int j = 0; j < 8; j++) acc[i][j] = 0.f;

    // A-load assignment: thread handles row ar, cols [ac, ac+8)
    int ar = tid >> 1;
    int ac = (tid & 1) * 8;
    int atok = rows[ar];
    // B-load assignment: row br, cols [bc, bc+8)
    int br = tid >> 4;
    int bc = (tid & 15) * 8;

    const float* Bbase = w1 + (size_t)e * D * F + col0;

    for (int k0 = 0; k0 < D; k0 += BK) {
        float4 av0 = make_float4(0.f, 0.f, 0.f, 0.f), av1 = av0;
        if (atok >= 0) {
            const float4* ap = (const float4*)(x + (size_t)atok * D + k0 + ac);
            av0 = ap[0]; av1 = ap[1];
        }
        const float4* bp = (const float4*)(Bbase + (size_t)(k0 + br) * F + bc);
        float4 bv0 = bp[0], bv1 = bp[1];

        As[ac + 0][ar] = av0.x; As[ac + 1][ar] = av0.y;
        As[ac + 2][ar] = av0.z; As[ac + 3][ar] = av0.w;
        As[ac + 4][ar] = av1.x; As[ac + 5][ar] = av1.y;
        As[ac + 6][ar] = av1.z; As[ac + 7][ar] = av1.w;
        *(float4*)&Bs[br][bc]     = bv0;
        *(float4*)&Bs[br][bc + 4] = bv1;
        __syncthreads();

        #pragma unroll
        for (int k = 0; k < BK; k++) {
            float4 A0 = *(const float4*)&As[k][ty * 4];
            float4 A1 = *(const float4*)&As[k][ty * 4 + 64];
            float4 B0 = *(const float4*)&Bs[k][tx * 4];
            float4 B1 = *(const float4*)&Bs[k][tx * 4 + 64];
            float axv[8] = {A0.x, A0.y, A0.z, A0.w, A1.x, A1.y, A1.z, A1.w};
            float bxv[8] = {B0.x, B0.y, B0.z, B0.w, B1.x, B1.y, B1.z, B1.w};
            #pragma unroll
            for (int i = 0; i < 8; i++)
                #pragma unroll
                for (int j = 0; j < 8; j++)
                    acc[i][j] = fmaf(axv[i], bxv[j], acc[i][j]);
        }
        __syncthreads();
    }

    // epilogue: bias + exact-erf gelu -> hbuf
    #pragma unroll
    for (int i = 0; i < 8; i++) {
        int rloc = (i < 4) ? (ty * 4 + i) : (64 + ty * 4 + (i - 4));
        int r = row0 + rloc;
        if (r >= cnt) continue;
        int slot = g_slot[e * NTOK + r];
        float* hrow = g_hbuf + (size_t)slot * F + col0;
        #pragma unroll
        for (int j = 0; j < 8; j++) {
            int cloc = (j < 4) ? (tx * 4 + j) : (64 + tx * 4 + (j - 4));
            float val = acc[i][j] + b1[e * F + col0 + cloc];
            hrow[cloc] = 0.5f * val * (1.0f + erff(val * 0.70710678118654752f));
        }
    }
}

// ---------------- GEMM2: out[tok] += ce * (H[slot] @ w2[e] + b2[e]) ----------------
__global__ __launch_bounds__(256) void gemm2_kernel(
    const float* __restrict__ w2, const float* __restrict__ b2,
    float* __restrict__ out) {
    int e    = blockIdx.z;
    int cnt  = g_cnt[e];
    int row0 = blockIdx.y * BM;
    if (row0 >= cnt) return;
    int col0 = blockIdx.x * BN;

    __shared__ float As[BK][BM];
    __shared__ float Bs[BK][BN];
    __shared__ int   slots[BM];
    __shared__ int   toks[BM];
    __shared__ float wts[BM];

    int tid = threadIdx.x;
    if (tid < BM) {
        int r = row0 + tid;
        if (r < cnt) {
            slots[tid] = g_slot[e * NTOK + r];
            toks[tid]  = g_tok[e * NTOK + r];
            wts[tid]   = g_wt[e * NTOK + r];
        } else {
            slots[tid] = -1; toks[tid] = 0; wts[tid] = 0.f;
        }
    }
    __syncthreads();

    int ty = tid >> 4, tx = tid & 15;
    float acc[8][8];
    #pragma unroll
    for (int i = 0; i < 8; i++)
        #pragma unroll
        for (int j = 0; j < 8; j++) acc[i][j] = 0.f;

    int ar = tid >> 1;
    int ac = (tid & 1) * 8;
    int aslot = slots[ar];
    int br = tid >> 4;
    int bc = (tid & 15) * 8;

    const float* Bbase = w2 + (size_t)e * F * D + col0;

    for (int k0 = 0; k0 < F; k0 += BK) {
        float4 av0 = make_float4(0.f, 0.f, 0.f, 0.f), av1 = av0;
        if (aslot >= 0) {
            const float4* ap = (const float4*)(g_hbuf + (size_t)aslot * F + k0 + ac);
            av0 = ap[0]; av1 = ap[1];
        }
        const float4* bp = (const float4*)(Bbase + (size_t)(k0 + br) * D + bc);
        float4 bv0 = bp[0], bv1 = bp[1];

        As[ac + 0][ar] = av0.x; As[ac + 1][ar] = av0.y;
        As[ac + 2][ar] = av0.z; As[ac + 3][ar] = av0.w;
        As[ac + 4][ar] = av1.x; As[ac + 5][ar] = av1.y;
        As[ac + 6][ar] = av1.z; As[ac + 7][ar] = av1.w;
        *(float4*)&Bs[br][bc]     = bv0;
        *(float4*)&Bs[br][bc + 4] = bv1;
        __syncthreads();

        #pragma unroll
        for (int k = 0; k < BK; k++) {
            float4 A0 = *(const float4*)&As[k][ty * 4];
            float4 A1 = *(const float4*)&As[k][ty * 4 + 64];
            float4 B0 = *(const float4*)&Bs[k][tx * 4];
            float4 B1 = *(const float4*)&Bs[k][tx * 4 + 64];
            float axv[8] = {A0.x, A0.y, A0.z, A0.w, A1.x, A1.y, A1.z, A1.w};
            float bxv[8] = {B0.x, B0.y, B0.z, B0.w, B1.x, B1.y, B1.z, B1.w};
            #pragma unroll
            for (int i = 0; i < 8; i++)
                #pragma unroll
                for (int j = 0; j < 8; j++)
                    acc[i][j] = fmaf(axv[i], bxv[j], acc[i][j]);
        }
        __syncthreads();
    }

    #pragma unroll
    for (int i = 0; i < 8; i++) {
        int rloc = (i < 4) ? (ty * 4 + i) : (64 + ty * 4 + (i - 4));
        int r = row0 + rloc;
        if (r >= cnt) continue;
        int tok = toks[rloc];
        float w = wts[rloc];
        float* orow = out + (size_t)tok * D + col0;
        #pragma unroll
        for (int j = 0; j < 8; j++) {
            int cloc = (j < 4) ? (tx * 4 + j) : (64 + tx * 4 + (j - 4));
            float val = (acc[i][j] + b2[e * D + col0 + cloc]) * w;
            atomicAdd(&orow[cloc], val);
        }
    }
}

// ---------------- aux loss scalar ----------------
__global__ void aux_kernel(const float* __restrict__ load_ema,
                           float* __restrict__ out_aux) {
    float base = 0.f;
    for (int e = 0; e < NE; e++) {
        float frac = ((float)g_cnt[e] / (float)NTOK) / (float)TK;
        float pm   = g_probs_sum[e] / (float)NTOK;
        base += frac * pm;
    }
    base *= (float)NE;
    float s = 0.f;
    for (int e = 0; e < NE; e++) s += load_ema[e];
    float ent = 0.f;
    for (int e = 0; e < NE; e++) {
        float lp = load_ema[e] / (s + 1e-8f);
        ent -= lp * logf(lp + 1e-8f);
    }
    float reg = logf((float)NE) - ent;
    out_aux[0] = base + 0.001f * reg;
}

// ---------------- launch ----------------
extern "C" void kernel_launch(void* const* d_in, const int* in_sizes, int n_in,
                              void* d_out, int out_size) {
    const float* x   = (const float*)d_in[0];
    const float* gw  = (const float*)d_in[1];
    const float* gb  = (const float*)d_in[2];
    const float* w1  = (const float*)d_in[3];
    const float* b1  = (const float*)d_in[4];
    const float* w2  = (const float*)d_in[5];
    const float* b2  = (const float*)d_in[6];
    const float* ema = (const float*)d_in[7];
    float* out = (float*)d_out;

    const int nOut = NTOK * D;

    zero_kernel<<<(nOut + 255) / 256, 256>>>(out, nOut);
    router_kernel<<<NTOK, 32>>>(x, gw, gb);
    gemm1_kernel<<<dim3(F / BN, NTOK / BM, NE), 256>>>(x, w1, b1);
    gemm2_kernel<<<dim3(D / BN, NTOK / BM, NE), 256>>>(w2, b2, out);
    if (out_size > nOut) {
        aux_kernel<<<1, 1>>>(ema, out + nOut);
    }
}